// round 1
// baseline (speedup 1.0000x reference)
#include <cuda_runtime.h>

#define Tlen 1000
#define Bsz  4096
#define INsz 8
#define Hsz  50
#define Osz  6
#define NDIM 56        // 50 h dims + 6 y dims
#define WROW 60        // weight row: [0..49]=W_rec/W_out, [50,51]=0, [52..59]=W_in/0
#define VROW 68        // v row stride in floats (17 x 16B -> conflict-free)
#define BTILE 32
#define NPAIR 16

__device__ __forceinline__ void fma2(unsigned long long& acc,
                                     unsigned long long a,
                                     unsigned long long b) {
    asm("fma.rn.f32x2 %0, %1, %2, %0;" : "+l"(acc) : "l"(a), "l"(b));
}

__device__ __forceinline__ float hadd2(unsigned long long a) {
    float lo, hi;
    asm("mov.b64 {%0, %1}, %2;" : "=f"(lo), "=f"(hi) : "l"(a));
    return lo + hi;
}

__global__ void __launch_bounds__(128, 1) biornn_kernel(
    const float* __restrict__ x,       // (T, B, 8)
    const float* __restrict__ W_in,    // (50, 8)
    const float* __restrict__ W_rec,   // (50, 50)
    const float* __restrict__ bias,    // (50,)
    const float* __restrict__ W_out_w, // (6, 50)
    const float* __restrict__ W_out_b, // (6,)
    float* __restrict__ out)           // (T, B, 6)
{
    __shared__ __align__(16) float sW[NDIM * WROW];
    __shared__ __align__(16) float sV[2 * BTILE * VROW];
    __shared__ float sB[NDIM];

    const int tid = threadIdx.x;

    // ---- stage weights (concatenated + padded) into shared ----
    for (int i = tid; i < NDIM * WROW; i += 128) {
        int d = i / WROW, j = i - d * WROW;
        float w = 0.f;
        if (d < Hsz) {
            if (j < Hsz)       w = W_rec[d * Hsz + j];
            else if (j >= 52)  w = W_in[d * INsz + (j - 52)];
        } else {
            if (j < Hsz)       w = W_out_w[(d - Hsz) * Hsz + j];
        }
        sW[i] = w;
    }
    // zero v buffers once (pads j=50,51 must stay 0 forever)
    for (int i = tid; i < 2 * BTILE * VROW; i += 128) sV[i] = 0.f;
    for (int i = tid; i < NDIM; i += 128)
        sB[i] = (i < Hsz) ? bias[i] : W_out_b[i - Hsz];
    __syncthreads();

    const int p  = tid & 15;   // batch-pair id within tile
    const int g  = tid >> 4;   // dim group (7 dims each)
    const int b0 = p;
    const int b1 = p + NPAIR;
    const int gb0 = blockIdx.x * BTILE;   // global batch base

    float hA[7], hB[7], br[7];
    #pragma unroll
    for (int dl = 0; dl < 7; dl++) {
        hA[dl] = 0.f; hB[dl] = 0.f;
        br[dl] = sB[g * 7 + dl];
    }

    const float* wbase = sW + g * 7 * WROW;

    // ---- prefetch x for t = 0 into registers (only dim-group 0 handles x) ----
    float4 xa0, xa1, xc0, xc1;
    if (g == 0) {
        const float4* xp = reinterpret_cast<const float4*>(x);
        size_t base = ((size_t)0 * Bsz + gb0) * 2;   // 2 float4 per batch elem
        xa0 = xp[base + (size_t)b0 * 2 + 0];
        xa1 = xp[base + (size_t)b0 * 2 + 1];
        xc0 = xp[base + (size_t)b1 * 2 + 0];
        xc1 = xp[base + (size_t)b1 * 2 + 1];
    }

    #pragma unroll 1
    for (int t = 0; t < Tlen; t++) {
        float* vb  = sV + (t & 1) * (BTILE * VROW);
        float* vr0 = vb + b0 * VROW;
        float* vr1 = vb + b1 * VROW;

        // ---- publish r = relu(h) for owned h dims ----
        if (g < 7) {
            #pragma unroll
            for (int dl = 0; dl < 7; dl++) {
                vr0[g * 7 + dl] = fmaxf(hA[dl], 0.f);
                vr1[g * 7 + dl] = fmaxf(hB[dl], 0.f);
            }
        } else {
            vr0[49] = fmaxf(hA[0], 0.f);
            vr1[49] = fmaxf(hB[0], 0.f);
        }

        // ---- publish x_t (from regs), prefetch x_{t+1} ----
        if (g == 0) {
            *reinterpret_cast<float4*>(vr0 + 52) = xa0;
            *reinterpret_cast<float4*>(vr0 + 56) = xa1;
            *reinterpret_cast<float4*>(vr1 + 52) = xc0;
            *reinterpret_cast<float4*>(vr1 + 56) = xc1;
            if (t + 1 < Tlen) {
                const float4* xp = reinterpret_cast<const float4*>(x);
                size_t base = ((size_t)(t + 1) * Bsz + gb0) * 2;
                xa0 = xp[base + (size_t)b0 * 2 + 0];
                xa1 = xp[base + (size_t)b0 * 2 + 1];
                xc0 = xp[base + (size_t)b1 * 2 + 0];
                xc1 = xp[base + (size_t)b1 * 2 + 1];
            }
        }
        __syncthreads();   // single barrier per step (double-buffered v)

        // ---- fused matvec: 7 dims x 2 batches, f32x2 packed along j ----
        unsigned long long accA[7], accB[7];
        #pragma unroll
        for (int dl = 0; dl < 7; dl++) { accA[dl] = 0ull; accB[dl] = 0ull; }

        const ulonglong2* va = reinterpret_cast<const ulonglong2*>(vr0);
        const ulonglong2* vc = reinterpret_cast<const ulonglong2*>(vr1);
        #pragma unroll
        for (int jb = 0; jb < 15; jb++) {
            ulonglong2 a = va[jb];
            ulonglong2 c = vc[jb];
            #pragma unroll
            for (int dl = 0; dl < 7; dl++) {
                ulonglong2 w =
                    reinterpret_cast<const ulonglong2*>(wbase + dl * WROW)[jb];
                fma2(accA[dl], a.x, w.x);
                fma2(accA[dl], a.y, w.y);
                fma2(accB[dl], c.x, w.x);
                fma2(accB[dl], c.y, w.y);
            }
        }

        // ---- finalize: h update (dims < 50) / y output (dims 50..55) ----
        if (g < 7) {
            #pragma unroll
            for (int dl = 0; dl < 7; dl++) {
                float sA = hadd2(accA[dl]) + br[dl];
                float sC = hadd2(accB[dl]) + br[dl];
                hA[dl] = fmaf(0.1f, sA - hA[dl], hA[dl]);
                hB[dl] = fmaf(0.1f, sC - hB[dl], hB[dl]);
            }
        } else {
            {   // dim 49 is an h dim
                float sA = hadd2(accA[0]) + br[0];
                float sC = hadd2(accB[0]) + br[0];
                hA[0] = fmaf(0.1f, sA - hA[0], hA[0]);
                hB[0] = fmaf(0.1f, sC - hB[0], hB[0]);
            }
            size_t ob = ((size_t)t * Bsz + gb0) * Osz;
            #pragma unroll
            for (int dl = 1; dl < 7; dl++) {
                out[ob + (size_t)b0 * Osz + (dl - 1)] = hadd2(accA[dl]) + br[dl];
                out[ob + (size_t)b1 * Osz + (dl - 1)] = hadd2(accB[dl]) + br[dl];
            }
        }
    }
}

extern "C" void kernel_launch(void* const* d_in, const int* in_sizes, int n_in,
                              void* d_out, int out_size) {
    const float* x        = (const float*)d_in[0];
    const float* W_in     = (const float*)d_in[1];
    const float* W_rec    = (const float*)d_in[2];
    const float* bias     = (const float*)d_in[3];
    const float* W_out_w  = (const float*)d_in[4];
    const float* W_out_b  = (const float*)d_in[5];
    float* out = (float*)d_out;

    biornn_kernel<<<Bsz / BTILE, 128>>>(x, W_in, W_rec, bias,
                                        W_out_w, W_out_b, out);
}